// round 1
// baseline (speedup 1.0000x reference)
#include <cuda_runtime.h>
#include <math.h>

#define BB   4
#define LL   1024
#define HIDD 768
#define HH   12
#define DD   64
#define BH   (BB*HH)

// ---- scratch (device globals; no allocation allowed) ----
__device__ float g_q[BH * LL * DD];          // [bh, l, d]
__device__ float g_k[BH * LL * DD];
__device__ float g_v[BH * LL * DD];
__device__ float g_scores[(size_t)BH * LL * LL];  // [bh, l, r]  (201 MB)

// ============================================================================
// K1: QKV projection.  Y = X @ W^T + b, scattered into [B,H,L,D].
// X: [4096, 768] row-major.  W: [768, 768] row-major (Y[i,j] = sum_k X[i,k]W[j,k]).
// Classic 128x128x8 SGEMM, 256 threads, 8x8 per-thread microtile.
// ============================================================================
__global__ __launch_bounds__(256) void qkv_kernel(
    const float* __restrict__ X,
    const float* __restrict__ W,
    const float* __restrict__ bias,
    int which)
{
    __shared__ float As[8][132];   // [kk][m], padded: conflict-free stores & reads
    __shared__ float Bs[8][132];   // [kk][n]

    const int tid = threadIdx.x;
    const int m0 = blockIdx.x * 128;
    const int n0 = blockIdx.y * 128;
    const int tx = tid & 15;       // n-direction
    const int ty = tid >> 4;       // m-direction

    float acc[8][8];
#pragma unroll
    for (int i = 0; i < 8; i++)
#pragma unroll
        for (int j = 0; j < 8; j++) acc[i][j] = 0.f;

    const int lrow = tid >> 1;        // 0..127
    const int lc   = (tid & 1) * 4;   // 0 or 4
    const float* Xp = X + (size_t)(m0 + lrow) * HIDD + lc;
    const float* Wp = W + (size_t)(n0 + lrow) * HIDD + lc;

    for (int k0 = 0; k0 < HIDD; k0 += 8) {
        float4 av = *(const float4*)(Xp + k0);
        float4 bv = *(const float4*)(Wp + k0);
        __syncthreads();
        As[lc + 0][lrow] = av.x; As[lc + 1][lrow] = av.y;
        As[lc + 2][lrow] = av.z; As[lc + 3][lrow] = av.w;
        Bs[lc + 0][lrow] = bv.x; Bs[lc + 1][lrow] = bv.y;
        Bs[lc + 2][lrow] = bv.z; Bs[lc + 3][lrow] = bv.w;
        __syncthreads();
#pragma unroll
        for (int kk = 0; kk < 8; kk++) {
            float a[8], b[8];
#pragma unroll
            for (int i = 0; i < 4; i++) {
                a[i]     = As[kk][tx * 0 + ty * 4 + i];   // rows ty*4+i
                a[4 + i] = As[kk][64 + ty * 4 + i];       // rows 64+ty*4+i
            }
#pragma unroll
            for (int j = 0; j < 4; j++) {
                b[j]     = Bs[kk][tx * 4 + j];
                b[4 + j] = Bs[kk][64 + tx * 4 + j];
            }
#pragma unroll
            for (int i = 0; i < 8; i++)
#pragma unroll
                for (int j = 0; j < 8; j++)
                    acc[i][j] = fmaf(a[i], b[j], acc[i][j]);
        }
    }

    float* out = (which == 0) ? g_q : (which == 1) ? g_k : g_v;
#pragma unroll
    for (int i = 0; i < 8; i++) {
        const int m = m0 + ((i < 4) ? (ty * 4 + i) : (64 + ty * 4 + (i - 4)));
        const int b_idx = m >> 10;       // / L
        const int l     = m & (LL - 1);
#pragma unroll
        for (int j = 0; j < 8; j++) {
            const int n = n0 + ((j < 4) ? (tx * 4 + j) : (64 + tx * 4 + (j - 4)));
            const int h = n >> 6;
            const int d = n & 63;
            out[(((size_t)b_idx * HH + h) * LL + l) * DD + d] = acc[i][j] + bias[n];
        }
    }
}

// ============================================================================
// K2: scores[bh,l,r] = ( q.k + (q[l]+k[r]).S[l,r,:] ) * 0.125 + mask[b,r]
// 16x16 (l,r) tile per block; each thread owns one (l,r) pair and keeps
// S[l,r,0..63] in 64 registers, amortized across all 48 bh.  S read ONCE.
// ============================================================================
__global__ __launch_bounds__(256) void scores_kernel(
    const float* __restrict__ S,
    const float* __restrict__ mask)
{
    __shared__ float qs[64 * 17];   // [d][l], stride 17 -> conflict-free
    __shared__ float ks[64 * 17];   // [d][r]

    const int tid = threadIdx.x;
    const int l0 = blockIdx.y * 16;
    const int r0 = blockIdx.x * 16;
    const int li = tid >> 4;   // 0..15
    const int ri = tid & 15;

    // Load this thread's S row into registers (16 x float4, contiguous 256B)
    float sreg[64];
    {
        const float4* sp = (const float4*)(S + (((size_t)(l0 + li)) * LL + (r0 + ri)) * DD);
#pragma unroll
        for (int t = 0; t < 16; t++) {
            float4 v = sp[t];
            sreg[4 * t + 0] = v.x; sreg[4 * t + 1] = v.y;
            sreg[4 * t + 2] = v.z; sreg[4 * t + 3] = v.w;
        }
    }

    for (int bh = 0; bh < BH; bh++) {
        __syncthreads();
        // cooperative load of q tile (rows l0..l0+15) and k tile (rows r0..r0+15)
        for (int idx = tid; idx < 16 * 64; idx += 256) {
            const int row = idx >> 6;
            const int d   = idx & 63;
            qs[d * 17 + row] = g_q[((size_t)bh * LL + (l0 + row)) * DD + d];
            ks[d * 17 + row] = g_k[((size_t)bh * LL + (r0 + row)) * DD + d];
        }
        __syncthreads();

        float acc = 0.f;
#pragma unroll
        for (int d = 0; d < 64; d++) {
            const float qv = qs[d * 17 + li];
            const float kv = ks[d * 17 + ri];
            acc = fmaf(qv, kv, acc);
            acc = fmaf(qv + kv, sreg[d], acc);
        }
        const int b_idx = bh / HH;
        g_scores[((size_t)bh * LL + (l0 + li)) * LL + (r0 + ri)] =
            acc * 0.125f + mask[b_idx * LL + (r0 + ri)];
    }
}

// ============================================================================
// K3: row softmax over r, then ctx = P @ V, written to [B, L, H*D].
// Block = (bh, 64 l-rows). Phase 1: warp-per-row max & sum (gmem pass).
// Phase 2: P recomputed into smem per 64-wide r-chunk, 4x4 microtile P@V.
// ============================================================================
__global__ __launch_bounds__(256) void softmax_pv_kernel(float* __restrict__ out)
{
    __shared__ __align__(16) float Vs[64 * 68];   // [r][d] pad 68 (float4 ok)
    __shared__ float Ps[64 * 67];                 // [r][l] pad 67 (conflict-free STS)
    __shared__ float rmax[64], rinv[64];

    const int tid  = threadIdx.x;
    const int bh   = blockIdx.y;
    const int l0   = blockIdx.x * 64;
    const int warp = tid >> 5;
    const int lane = tid & 31;

    const float* srow_base = g_scores + ((size_t)bh * LL + l0) * LL;

    // ---- phase 1: per-row max and sum(exp) ----
    for (int rr = warp; rr < 64; rr += 8) {
        const float* srow = srow_base + (size_t)rr * LL;
        float v[32];
#pragma unroll
        for (int j = 0; j < 32; j++) v[j] = srow[lane + 32 * j];
        float m = -1e30f;
#pragma unroll
        for (int j = 0; j < 32; j++) m = fmaxf(m, v[j]);
#pragma unroll
        for (int o = 16; o > 0; o >>= 1) m = fmaxf(m, __shfl_xor_sync(0xffffffffu, m, o));
        float s = 0.f;
#pragma unroll
        for (int j = 0; j < 32; j++) s += __expf(v[j] - m);
#pragma unroll
        for (int o = 16; o > 0; o >>= 1) s += __shfl_xor_sync(0xffffffffu, s, o);
        if (lane == 0) { rmax[rr] = m; rinv[rr] = 1.f / s; }
    }
    __syncthreads();

    // ---- phase 2: P @ V ----
    const int tx = tid & 15;   // d-direction (4 cols)
    const int ty = tid >> 4;   // l-direction (4 rows)
    float acc[4][4];
#pragma unroll
    for (int i = 0; i < 4; i++)
#pragma unroll
        for (int j = 0; j < 4; j++) acc[i][j] = 0.f;

    for (int rc = 0; rc < LL; rc += 64) {
        __syncthreads();
        // V chunk: rows rc..rc+63, all 64 d
        {
            const float4* vp = (const float4*)(g_v + ((size_t)bh * LL + rc) * DD);
            for (int idx = tid; idx < 64 * 16; idx += 256) {
                const int r  = idx >> 4;
                const int c4 = idx & 15;
                *(float4*)&Vs[r * 68 + c4 * 4] = vp[r * 16 + c4];
            }
        }
        // P chunk (exp recompute): Ps[k][l]
        for (int idx = tid; idx < 64 * 64; idx += 256) {
            const int l = idx >> 6;
            const int k = idx & 63;
            const float sc = srow_base[(size_t)l * LL + rc + k];
            Ps[k * 67 + l] = __expf(sc - rmax[l]);
        }
        __syncthreads();

#pragma unroll 8
        for (int k = 0; k < 64; k++) {
            float p[4];
#pragma unroll
            for (int i = 0; i < 4; i++) p[i] = Ps[k * 67 + ty * 4 + i];
            const float4 v4 = *(const float4*)&Vs[k * 68 + tx * 4];
            const float vv[4] = { v4.x, v4.y, v4.z, v4.w };
#pragma unroll
            for (int i = 0; i < 4; i++)
#pragma unroll
                for (int j = 0; j < 4; j++)
                    acc[i][j] = fmaf(p[i], vv[j], acc[i][j]);
        }
    }

    // ---- write: out[b, l, h*64 + d] ----
    const int b_idx = bh / HH;
    const int h     = bh % HH;
#pragma unroll
    for (int i = 0; i < 4; i++) {
        const int lrow = ty * 4 + i;
        const float inv = rinv[lrow];
        const int l = l0 + lrow;
#pragma unroll
        for (int j = 0; j < 4; j++) {
            const int d = tx * 4 + j;
            out[((size_t)(b_idx * LL + l)) * HIDD + h * DD + d] = acc[i][j] * inv;
        }
    }
}

// ============================================================================
// launch
// ============================================================================
extern "C" void kernel_launch(void* const* d_in, const int* in_sizes, int n_in,
                              void* d_out, int out_size)
{
    (void)in_sizes; (void)n_in; (void)out_size;
    const float* hidden = (const float*)d_in[0];
    const float* mask   = (const float*)d_in[1];
    const float* S      = (const float*)d_in[2];
    const float* Wq     = (const float*)d_in[3];
    const float* bq     = (const float*)d_in[4];
    const float* Wk     = (const float*)d_in[5];
    const float* bk     = (const float*)d_in[6];
    const float* Wv     = (const float*)d_in[7];
    const float* bv     = (const float*)d_in[8];
    float* out = (float*)d_out;

    dim3 g1(32, 6);                 // (B*L)/128, HID/128
    qkv_kernel<<<g1, 256>>>(hidden, Wq, bq, 0);
    qkv_kernel<<<g1, 256>>>(hidden, Wk, bk, 1);
    qkv_kernel<<<g1, 256>>>(hidden, Wv, bv, 2);

    dim3 g2(LL / 16, LL / 16);      // (r tiles, l tiles)
    scores_kernel<<<g2, 256>>>(S, mask);

    dim3 g3(LL / 64, BH);           // (l tiles, bh)
    softmax_pv_kernel<<<g3, 256>>>(out);
}